// round 12
// baseline (speedup 1.0000x reference)
#include <cuda_runtime.h>
#include <cuda_fp16.h>

#define NI 2000      // inner tree nodes
#define NL 10000     // leaves / vocab
#define ND 128       // docs
#define PP 2048      // padded proj width
#define FC 64        // mass feature chunk
#define NMASS_CH 157 // ceil(NL/FC)
#define AG_BLKS 400  // argmax: 10 float4-col blocks x 40 row-chunks
#define AG_CH 50     // rows per argmax chunk
#define AG_RB 10     // load batch (MLP)
#define MP1_CH 79    // masspair chunks in fused1 (0..78)
#define MP1_BLKS (3 * MP1_CH)              // 237
#define MP2_BLKS (3 * (NMASS_CH - MP1_CH)) // 234
#define SROWH 68     // half2 row stride per feature-pair
// scatter: 64 docpairs x 4 leaf-slices
#define SC_BLKS 256
#define SLLEN 625    // float4-leaves per slice (2500/4)
// proj-pair (R4-measured config): 32-doc tiles, 64-f chunks, 2x2 micro
#define PT 32
#define PSROW 36
#define NPP 10
#define PP_BLKS (NPP * (PP / FC))   // 320

__device__ unsigned long long g_amax[NL];
__device__ float g_proj[ND * PP];
__device__ float g_S[ND];

__constant__ int c_it[NPP] = {0,0,0,0,1,1,1,2,2,3};
__constant__ int c_jt[NPP] = {0,1,2,3,1,2,3,2,3,3};

__device__ __forceinline__ __half2 u2h2(unsigned u) {
    return *reinterpret_cast<__half2*>(&u);
}
__device__ __forceinline__ unsigned long long pack_key(float v, int idx) {
    unsigned u = __float_as_uint(v);
    u = (u & 0x80000000u) ? ~u : (u | 0x80000000u);
    return ((unsigned long long)u << 32) | (unsigned)idx;
}
__device__ __forceinline__ void red4(float* p, float4 v) {
    asm volatile("red.global.add.v4.f32 [%0], {%1,%2,%3,%4};"
                 :: "l"(p), "f"(v.x), "f"(v.y), "f"(v.z), "f"(v.w) : "memory");
}

// ---------------------------------------------------------------- init
__global__ void k_init(float* __restrict__ out) {
    int i = blockIdx.x * blockDim.x + threadIdx.x;
    if (i < ND * PP) g_proj[i] = 0.0f;
    if (i < NL) g_amax[i] = 0ull;
    if (i < ND * ND) out[i] = 0.0f;
    if (i < ND) g_S[i] = 0.0f;
}

// ---------------------------------------------------------------- fp16 mass-pair worker (one 64-f chunk, 64x64 tile-pair)
__device__ __forceinline__ void masspair_block(
    const float* __restrict__ mass, float* __restrict__ out,
    int pid, __half2* sa2, __half2* sb2)
{
    int tp = pid % 3;                 // 0:(0,0) 1:(0,1)+mirror 2:(1,1)
    int chunk = pid / 3;
    int fb = chunk * FC;
    int nh = min(FC, NL - fb) >> 1;   // valid half2 feature-pairs
    int it = (tp == 2) ? 1 : 0;
    int jt = (tp == 0) ? 0 : 1;
    int tid = threadIdx.x;

    const __half2 hz = __float2half2_rn(0.0f);
    #pragma unroll
    for (int k = 0; k < 8; k++) {
        int idx = tid + k * 256;          // 0..2047
        int f2 = idx & 31;
        int row = idx >> 5;               // 0..63
        __half2 ha = hz, hb = hz;
        if (f2 < nh) {
            float2 va = *(const float2*)&mass[(size_t)(it * 64 + row) * NL + fb + 2 * f2];
            float2 vb = *(const float2*)&mass[(size_t)(jt * 64 + row) * NL + fb + 2 * f2];
            ha = __floats2half2_rn(va.x, va.y);
            hb = __floats2half2_rn(vb.x, vb.y);
        }
        sa2[f2 * SROWH + row] = ha;
        sb2[f2 * SROWH + row] = hb;
    }
    __syncthreads();

    int tx = tid & 15, ty = tid >> 4;
    __half2 acc[4][4];
    #pragma unroll
    for (int r = 0; r < 4; r++)
        #pragma unroll
        for (int c = 0; c < 4; c++) acc[r][c] = hz;

    #pragma unroll 4
    for (int f2 = 0; f2 < 32; f2++) {
        uint4 ua = *(const uint4*)&sa2[f2 * SROWH + ty * 4];
        uint4 ub = *(const uint4*)&sb2[f2 * SROWH + tx * 4];
        __half2 ar[4] = {u2h2(ua.x), u2h2(ua.y), u2h2(ua.z), u2h2(ua.w)};
        __half2 br[4] = {u2h2(ub.x), u2h2(ub.y), u2h2(ub.z), u2h2(ub.w)};
        #pragma unroll
        for (int r = 0; r < 4; r++)
            #pragma unroll
            for (int c = 0; c < 4; c++)
                acc[r][c] = __hadd2(acc[r][c], __hmin2(ar[r], br[c]));
    }

    int ib = it * 64 + ty * 4, jb = jt * 64 + tx * 4;
    #pragma unroll
    for (int r = 0; r < 4; r++)
        #pragma unroll
        for (int c = 0; c < 4; c++) {
            float2 f = __half22float2(acc[r][c]);
            float v = -2.0f * (f.x + f.y);
            atomicAdd(&out[(ib + r) * ND + (jb + c)], v);
            if (tp == 1)
                atomicAdd(&out[(jb + c) * ND + (ib + r)], v);
        }
}

// ---------------------------------------------------------------- fused1: argmax (batch-10 MLP) || masspair chunks 0..78
__global__ void __launch_bounds__(256)
k_fused1(const float* __restrict__ mass, const float* __restrict__ param,
         float* __restrict__ out) {
    __shared__ __half2 smp[2][32 * SROWH];
    if (blockIdx.x < AG_BLKS) {
        int bid = blockIdx.x;
        int j4 = (bid % 10) * 256 + threadIdx.x;    // float4 column
        if (j4 >= NL / 4) return;
        int r0 = (bid / 10) * AG_CH;
        const float4* p = (const float4*)param + (size_t)r0 * (NL / 4) + j4;
        float4 bv = make_float4(-3.4e38f, -3.4e38f, -3.4e38f, -3.4e38f);
        int ix = r0, iy = r0, iz = r0, iw = r0;
        for (int rb = 0; rb < AG_CH; rb += AG_RB) {
            float4 v[AG_RB];
            #pragma unroll
            for (int k = 0; k < AG_RB; k++)
                v[k] = p[(size_t)(rb + k) * (NL / 4)];
            #pragma unroll
            for (int k = 0; k < AG_RB; k++) {
                int r = r0 + rb + k;
                if (v[k].x > bv.x) { bv.x = v[k].x; ix = r; }
                if (v[k].y > bv.y) { bv.y = v[k].y; iy = r; }
                if (v[k].z > bv.z) { bv.z = v[k].z; iz = r; }
                if (v[k].w > bv.w) { bv.w = v[k].w; iw = r; }
            }
        }
        int j = 4 * j4;
        atomicMax(&g_amax[j + 0], pack_key(bv.x, ix));
        atomicMax(&g_amax[j + 1], pack_key(bv.y, iy));
        atomicMax(&g_amax[j + 2], pack_key(bv.z, iz));
        atomicMax(&g_amax[j + 3], pack_key(bv.w, iw));
    } else {
        masspair_block(mass, out, blockIdx.x - AG_BLKS, smp[0], smp[1]);
    }
}

// ---------------------------------------------------------------- fused2: half2 scatter (2 docs, 4 slices) + fp32 treesum || masspair 79..156
__global__ void __launch_bounds__(256)
k_fused2(const float* __restrict__ mass, float* __restrict__ out) {
    __shared__ union {
        struct { __half2 s2[NI]; float s1[NI]; float red[256]; } pj;
        __half2 mp[2][32 * SROWH];
    } sm;
    int tid = threadIdx.x;

    if (blockIdx.x < SC_BLKS) {
        int dp = blockIdx.x >> 2;           // docpair 0..63
        int sl = blockIdx.x & 3;            // slice 0..3
        int d0 = 2 * dp, d1 = 2 * dp + 1;
        __half2* s2 = sm.pj.s2;
        float* s0 = (float*)sm.pj.s2;       // aliases s2: unpack in place
        float* s1 = sm.pj.s1;

        for (int i = tid; i < NI; i += 256) s2[i] = __float2half2_rn(0.0f);
        __syncthreads();

        // scatter slice: one half2 atomic carries both docs' mass for a leaf
        const float4* m0 = (const float4*)(mass + (size_t)d0 * NL);
        const float4* m1 = (const float4*)(mass + (size_t)d1 * NL);
        int base = sl * SLLEN;
        for (int j4 = base + tid; j4 < base + SLLEN; j4 += 256) {
            float4 v0 = m0[j4];
            float4 v1 = m1[j4];
            int a0 = (int)(unsigned)(__ldg(&g_amax[4 * j4 + 0]) & 0xFFFFFFFFull);
            int a1 = (int)(unsigned)(__ldg(&g_amax[4 * j4 + 1]) & 0xFFFFFFFFull);
            int a2 = (int)(unsigned)(__ldg(&g_amax[4 * j4 + 2]) & 0xFFFFFFFFull);
            int a3 = (int)(unsigned)(__ldg(&g_amax[4 * j4 + 3]) & 0xFFFFFFFFull);
            atomicAdd(&s2[a0], __floats2half2_rn(v0.x, v1.x));
            atomicAdd(&s2[a1], __floats2half2_rn(v0.y, v1.y));
            atomicAdd(&s2[a2], __floats2half2_rn(v0.z, v1.z));
            atomicAdd(&s2[a3], __floats2half2_rn(v0.w, v1.w));
        }
        __syncthreads();

        // unpack half2 -> fp32 (s0 in place, s1 separate)
        for (int i = tid; i < NI; i += 256) {
            float2 f = __half22float2(s2[i]);
            s0[i] = f.x;
            s1[i] = f.y;
        }
        __syncthreads();

        // bottom-up tree-sum (fp32, both docs)
        const int lo[5] = {156, 31, 6, 1, 0};
        const int hi[5] = {399, 155, 30, 5, 0};
        for (int L = 0; L < 5; L++) {
            for (int p = lo[L] + tid; p <= hi[L]; p += 256) {
                float a0 = s0[p], a1 = s1[p];
                int c0 = 5 * p + 1;
                #pragma unroll
                for (int c = 0; c < 5; c++)
                    if (c0 + c < NI) { a0 += s0[c0 + c]; a1 += s1[c0 + c]; }
                s0[p] = a0; s1[p] = a1;
            }
            __syncthreads();
        }

        // merge partial subtree sums into g_proj (spread REDG) + S partials
        float p0 = 0.0f, p1 = 0.0f;
        float* gp0 = g_proj + (size_t)d0 * PP;
        float* gp1 = g_proj + (size_t)d1 * PP;
        for (int i = tid * 4; i < NI; i += 1024) {
            float4 a = *(float4*)&s0[i];
            float4 b = *(float4*)&s1[i];
            p0 += a.x + a.y + a.z + a.w;
            p1 += b.x + b.y + b.z + b.w;
            red4(&gp0[i], a);
            red4(&gp1[i], b);
        }
        sm.pj.red[tid] = p0;
        __syncthreads();
        for (int w = 128; w > 0; w >>= 1) {
            if (tid < w) sm.pj.red[tid] += sm.pj.red[tid + w];
            __syncthreads();
        }
        if (tid == 0) atomicAdd(&g_S[d0], sm.pj.red[0]);
        __syncthreads();
        sm.pj.red[tid] = p1;
        __syncthreads();
        for (int w = 128; w > 0; w >>= 1) {
            if (tid < w) sm.pj.red[tid] += sm.pj.red[tid + w];
            __syncthreads();
        }
        if (tid == 0) atomicAdd(&g_S[d1], sm.pj.red[0]);
    } else {
        int pid = (blockIdx.x - SC_BLKS) + 3 * MP1_CH;   // chunks 79..156
        masspair_block(mass, out, pid, sm.mp[0], sm.mp[1]);
    }
}

// ---------------------------------------------------------------- fp32 proj-pair (32-tiles, 64-f chunks, 2x2) || S epilogue (+2 = mass sums)
__global__ void __launch_bounds__(256)
k_projpair(float* __restrict__ out) {
    __shared__ float sa[FC * PSROW];
    __shared__ float sb[FC * PSROW];
    if (blockIdx.x < PP_BLKS) {
        int pid = blockIdx.x;
        int tp = pid % NPP;
        int fb = (pid / NPP) * FC;
        int it = c_it[tp], jt = c_jt[tp];
        int tid = threadIdx.x;

        #pragma unroll
        for (int k = 0; k < 8; k++) {
            int idx = tid + k * 256;          // 0..2047 = 64 f x 32 rows
            int f = idx & 63;
            int row = idx >> 6;               // 0..31
            sa[f * PSROW + row] = g_proj[(size_t)(it * PT + row) * PP + fb + f];
            sb[f * PSROW + row] = g_proj[(size_t)(jt * PT + row) * PP + fb + f];
        }
        __syncthreads();

        int tx = tid & 15, ty = tid >> 4;
        float acc[2][2] = {{0.f, 0.f}, {0.f, 0.f}};
        #pragma unroll 8
        for (int f = 0; f < FC; f++) {
            float2 a = *(const float2*)&sa[f * PSROW + ty * 2];
            float2 b = *(const float2*)&sb[f * PSROW + tx * 2];
            acc[0][0] += fminf(a.x, b.x);
            acc[0][1] += fminf(a.x, b.y);
            acc[1][0] += fminf(a.y, b.x);
            acc[1][1] += fminf(a.y, b.y);
        }

        int ib = it * PT + ty * 2, jb = jt * PT + tx * 2;
        #pragma unroll
        for (int r = 0; r < 2; r++)
            #pragma unroll
            for (int c = 0; c < 2; c++) {
                float v = -2.0f * acc[r][c];
                atomicAdd(&out[(ib + r) * ND + (jb + c)], v);
                if (it != jt)
                    atomicAdd(&out[(jb + c) * ND + (ib + r)], v);
            }
    } else {
        int e = (blockIdx.x - PP_BLKS) * 256 + threadIdx.x;  // 0..16383
        // +2.0f = sum(mass_i) + sum(mass_j) (each doc's mass sums to 1)
        atomicAdd(&out[e], g_S[e >> 7] + g_S[e & 127] + 2.0f);
    }
}

// ---------------------------------------------------------------- launch
extern "C" void kernel_launch(void* const* d_in, const int* in_sizes, int n_in,
                              void* d_out, int out_size) {
    const float* mass  = (const float*)d_in[0];   // (128, 10000) f32
    const float* param = (const float*)d_in[1];   // (2000, 10000) f32
    float* out = (float*)d_out;                   // (128, 128) f32

    k_init<<<1024, 256>>>(out);
    k_fused1<<<AG_BLKS + MP1_BLKS, 256>>>(mass, param, out);
    k_fused2<<<SC_BLKS + MP2_BLKS, 256>>>(mass, out);
    k_projpair<<<PP_BLKS + (ND * ND) / 256, 256>>>(out);
}